// round 1
// baseline (speedup 1.0000x reference)
#include <cuda_runtime.h>

// out_b = x_b * M_b,  M_b = W^T * G_b,  G_b = x_b^T * x_b
// FLOPs: 77.3 GF (vs 309 GF naive), no [S,S] intermediate.

#define BM 128
#define BN 128
#define BK 8
#define TM 8
#define TN 8
// 256 threads = (BM/TM)*(BN/TN)

// Scratch (allocation-free rule: __device__ globals)
__device__ float g_G[4u * 1024u * 1024u];   // [B, H, H]
__device__ float g_Mt[4u * 1024u * 1024u];  // [B, H, H]

// C[M,N] = op(A)[M,K] * B[K,N], row-major C (ldc), B is (k,n)=B[k*ldb+n].
// TA=true : A(m,k) = A[k*lda + m]   (transposed operand, contiguous in m)
// TA=false: A(m,k) = A[m*lda + k]
template <bool TA>
__global__ __launch_bounds__(256, 2) void sgemm_kernel(
    const float* __restrict__ A, const float* __restrict__ B,
    float* __restrict__ C,
    int M, int N, int K, int lda, int ldb, int ldc,
    long strideA, long strideB, long strideC)
{
    __shared__ float As[BK][BM];
    __shared__ float Bs[BK][BN];

    const int bz = blockIdx.z;
    A += (long)bz * strideA;
    B += (long)bz * strideB;
    C += (long)bz * strideC;

    const int m0 = blockIdx.y * BM;
    const int n0 = blockIdx.x * BN;
    const int tid = threadIdx.x;

    const int tm = (tid / 16) * TM;
    const int tn = (tid % 16) * TN;

    float acc[TM][TN];
#pragma unroll
    for (int i = 0; i < TM; ++i)
#pragma unroll
        for (int j = 0; j < TN; ++j) acc[i][j] = 0.0f;

    for (int k0 = 0; k0 < K; k0 += BK) {
        // ---- load A tile into As[k][m] ----
        if (TA) {
            const int k = tid >> 5;          // 0..7
            const int m = (tid & 31) << 2;   // 0..124 step 4
            float4 v = *reinterpret_cast<const float4*>(
                &A[(long)(k0 + k) * lda + m0 + m]);
            *reinterpret_cast<float4*>(&As[k][m]) = v;
        } else {
            const int m  = tid >> 1;         // 0..127
            const int kq = (tid & 1) << 2;   // 0 or 4
            float4 v = *reinterpret_cast<const float4*>(
                &A[(long)(m0 + m) * lda + k0 + kq]);
            As[kq + 0][m] = v.x;
            As[kq + 1][m] = v.y;
            As[kq + 2][m] = v.z;
            As[kq + 3][m] = v.w;
        }
        // ---- load B tile into Bs[k][n] ----
        {
            const int k = tid >> 5;
            const int n = (tid & 31) << 2;
            float4 v = *reinterpret_cast<const float4*>(
                &B[(long)(k0 + k) * ldb + n0 + n]);
            *reinterpret_cast<float4*>(&Bs[k][n]) = v;
        }
        __syncthreads();

#pragma unroll
        for (int k = 0; k < BK; ++k) {
            float a[TM], b[TN];
            *reinterpret_cast<float4*>(&a[0]) =
                *reinterpret_cast<const float4*>(&As[k][tm]);
            *reinterpret_cast<float4*>(&a[4]) =
                *reinterpret_cast<const float4*>(&As[k][tm + 4]);
            *reinterpret_cast<float4*>(&b[0]) =
                *reinterpret_cast<const float4*>(&Bs[k][tn]);
            *reinterpret_cast<float4*>(&b[4]) =
                *reinterpret_cast<const float4*>(&Bs[k][tn + 4]);
#pragma unroll
            for (int i = 0; i < TM; ++i)
#pragma unroll
                for (int j = 0; j < TN; ++j)
                    acc[i][j] = fmaf(a[i], b[j], acc[i][j]);
        }
        __syncthreads();
    }

#pragma unroll
    for (int i = 0; i < TM; ++i) {
        float* cp = &C[(long)(m0 + tm + i) * ldc + n0 + tn];
        *reinterpret_cast<float4*>(cp)     = *reinterpret_cast<float4*>(&acc[i][0]);
        *reinterpret_cast<float4*>(cp + 4) = *reinterpret_cast<float4*>(&acc[i][4]);
    }
}

extern "C" void kernel_launch(void* const* d_in, const int* in_sizes, int n_in,
                              void* d_out, int out_size) {
    const float* x = (const float*)d_in[0];   // [B, S, H]
    const float* W = (const float*)d_in[1];   // [H, H]
    float* out = (float*)d_out;               // [B, S, H]

    const int S = 4096, H = 1024;
    const int B = in_sizes[0] / (S * H);      // 4

    float *G, *Mt;
    cudaGetSymbolAddress((void**)&G, g_G);
    cudaGetSymbolAddress((void**)&Mt, g_Mt);

    dim3 blk(256);

    // 1) G_b[o,h] = sum_t x[b,t,o] * x[b,t,h]   (M=N=H, K=S, A transposed)
    {
        dim3 grid(H / BN, H / BM, B);
        sgemm_kernel<true><<<grid, blk>>>(
            x, x, G, H, H, S, H, H, H,
            (long)S * H, (long)S * H, (long)H * H);
    }
    // 2) M_b[k,h] = sum_o W[o,k] * G_b[o,h]     (M=N=K=H, A transposed, W shared)
    {
        dim3 grid(H / BN, H / BM, B);
        sgemm_kernel<true><<<grid, blk>>>(
            W, G, Mt, H, H, H, H, H, H,
            0L, (long)H * H, (long)H * H);
    }
    // 3) out_b[s,h] = sum_k x[b,s,k] * M_b[k,h] (M=S, N=H, K=H)
    {
        dim3 grid(H / BN, S / BM, B);
        sgemm_kernel<false><<<grid, blk>>>(
            x, Mt, out, S, H, H, H, H, H,
            (long)S * H, (long)H * H, (long)S * H);
    }
}

// round 8
// speedup vs baseline: 2.5961x; 2.5961x over previous
#include <cuda_runtime.h>
#include <cuda_bf16.h>
#include <cstdint>

#define S_DIM 4096
#define H_DIM 1024
#define B_DIM 4

// ---------------- scratch (__device__ globals; no allocs allowed) -----------
__device__ __nv_bfloat16 g_xhi [B_DIM * S_DIM * H_DIM];
__device__ __nv_bfloat16 g_xlo [B_DIM * S_DIM * H_DIM];
__device__ __nv_bfloat16 g_xThi[B_DIM * H_DIM * S_DIM];
__device__ __nv_bfloat16 g_xTlo[B_DIM * H_DIM * S_DIM];
__device__ __nv_bfloat16 g_WThi[H_DIM * H_DIM];
__device__ __nv_bfloat16 g_WTlo[H_DIM * H_DIM];
__device__ __nv_bfloat16 g_Ghi [B_DIM * H_DIM * H_DIM];
__device__ __nv_bfloat16 g_Glo [B_DIM * H_DIM * H_DIM];
__device__ __nv_bfloat16 g_MThi[B_DIM * H_DIM * H_DIM];
__device__ __nv_bfloat16 g_MTlo[B_DIM * H_DIM * H_DIM];

// ---------------- helpers ----------------------------------------------------
__device__ __forceinline__ uint32_t smem_u32(const void* p) {
    uint32_t a;
    asm("{ .reg .u64 t; cvta.to.shared.u64 t, %1; cvt.u32.u64 %0, t; }"
        : "=r"(a) : "l"(p));
    return a;
}

#define SWZ128(off) ((off) ^ (((off) >> 3) & 0x70))

__device__ __forceinline__ void cp_async16(uint32_t dst, const void* src) {
    asm volatile("cp.async.cg.shared.global [%0], [%1], 16;" :: "r"(dst), "l"(src));
}

__device__ __forceinline__ void ldsm4(uint32_t* r, uint32_t addr) {
    asm volatile("ldmatrix.sync.aligned.m8n8.x4.shared.b16 {%0,%1,%2,%3}, [%4];"
                 : "=r"(r[0]), "=r"(r[1]), "=r"(r[2]), "=r"(r[3]) : "r"(addr));
}

__device__ __forceinline__ void mma_bf16(float* d, const uint32_t* a,
                                         uint32_t b0, uint32_t b1) {
    asm volatile(
        "mma.sync.aligned.m16n8k16.row.col.f32.bf16.bf16.f32 "
        "{%0,%1,%2,%3}, {%4,%5,%6,%7}, {%8,%9}, {%0,%1,%2,%3};"
        : "+f"(d[0]), "+f"(d[1]), "+f"(d[2]), "+f"(d[3])
        : "r"(a[0]), "r"(a[1]), "r"(a[2]), "r"(a[3]), "r"(b0), "r"(b1));
}

// ---------------- conversion kernels ----------------------------------------
__global__ void split_kernel(const float* __restrict__ in,
                             __nv_bfloat16* __restrict__ hi,
                             __nv_bfloat16* __restrict__ lo, int n4) {
    int i = blockIdx.x * blockDim.x + threadIdx.x;
    if (i >= n4) return;
    float4 v = reinterpret_cast<const float4*>(in)[i];
    __nv_bfloat16 h0 = __float2bfloat16(v.x), h1 = __float2bfloat16(v.y);
    __nv_bfloat16 h2 = __float2bfloat16(v.z), h3 = __float2bfloat16(v.w);
    __nv_bfloat16 l0 = __float2bfloat16(v.x - __bfloat162float(h0));
    __nv_bfloat16 l1 = __float2bfloat16(v.y - __bfloat162float(h1));
    __nv_bfloat16 l2 = __float2bfloat16(v.z - __bfloat162float(h2));
    __nv_bfloat16 l3 = __float2bfloat16(v.w - __bfloat162float(h3));
    reinterpret_cast<__nv_bfloat162*>(hi)[2 * i]     = __nv_bfloat162(h0, h1);
    reinterpret_cast<__nv_bfloat162*>(hi)[2 * i + 1] = __nv_bfloat162(h2, h3);
    reinterpret_cast<__nv_bfloat162*>(lo)[2 * i]     = __nv_bfloat162(l0, l1);
    reinterpret_cast<__nv_bfloat162*>(lo)[2 * i + 1] = __nv_bfloat162(l2, l3);
}

// in [R][C] -> out [C][R] with hi/lo split.  blockDim = (32, 8)
__global__ void transpose_split_kernel(const float* __restrict__ in,
                                       __nv_bfloat16* __restrict__ hi,
                                       __nv_bfloat16* __restrict__ lo,
                                       int R, int C) {
    __shared__ float tile[32][33];
    long boff = (long)blockIdx.z * R * C;
    const float* src = in + boff;
    int bx = blockIdx.x * 32;
    int by = blockIdx.y * 32;
    int tx = threadIdx.x, ty = threadIdx.y;
#pragma unroll
    for (int j = 0; j < 4; ++j)
        tile[ty + j * 8][tx] = src[(long)(by + ty + j * 8) * C + bx + tx];
    __syncthreads();
#pragma unroll
    for (int j = 0; j < 4; ++j) {
        int oc = bx + ty + j * 8;
        int orow = by + tx;
        float v = tile[tx][ty + j * 8];
        __nv_bfloat16 h = __float2bfloat16(v);
        __nv_bfloat16 l = __float2bfloat16(v - __bfloat162float(h));
        hi[boff + (long)oc * R + orow] = h;
        lo[boff + (long)oc * R + orow] = l;
    }
}

// ---------------- HMMA GEMM ---------------------------------------------------
// C[m][n] = sum_k (Ahi+Alo)[m][k]*(Bhi+Blo)[n][k], 3-term split (lo*lo dropped).
// CTA tile 128x128, KTILE=64 bf16 (128B rows, SW128), 3-stage cp.async.
// 8 warps (2x4), warp tile 64x32, mma.sync m16n8k16.
// MODE 0: write fp32 C.  MODE 1: write Chi/Clo bf16 split.

#define KTILE 64
#define TILE_BYTES 16384              // 128 rows * 128 B
#define STAGE_BYTES (4 * TILE_BYTES)  // Ahi, Alo, Bhi, Blo
#define NSTAGE 3
#define SMEM_TOT (NSTAGE * STAGE_BYTES)

template <int MODE>
__global__ __launch_bounds__(256, 1) void gemm_hmma3(
    const __nv_bfloat16* __restrict__ Ahi, const __nv_bfloat16* __restrict__ Alo,
    const __nv_bfloat16* __restrict__ Bhi, const __nv_bfloat16* __restrict__ Blo,
    float* __restrict__ C, __nv_bfloat16* __restrict__ Chi, __nv_bfloat16* __restrict__ Clo,
    int K, int lda, int ldb, int ldc, long sA, long sB, long sC)
{
    extern __shared__ char smem[];
    const uint32_t sbase = smem_u32(smem);
    const int tid = threadIdx.x;
    const int wid = tid >> 5;
    const int lane = tid & 31;
    const int warp_m = wid >> 2;   // 0..1
    const int warp_n = wid & 3;    // 0..3
    const int bz = blockIdx.z;
    const int m0 = blockIdx.y * 128;
    const int n0 = blockIdx.x * 128;

    const __nv_bfloat16* srcs[4];
    srcs[0] = Ahi + bz * sA + (long)m0 * lda;
    srcs[1] = Alo + bz * sA + (long)m0 * lda;
    srcs[2] = Bhi + bz * sB + (long)n0 * ldb;
    srcs[3] = Blo + bz * sB + (long)n0 * ldb;

    // ldmatrix per-lane base coordinates
    const int lr = lane & 7;
    const int lg = (lane >> 3) & 1;   // +8 row
    const int lk = (lane >> 4) & 1;   // +8 col (elements)
    const int arow = warp_m * 64 + lr + lg * 8;
    const int brow = warp_n * 32 + lr + lg * 8;
    const int colb0 = lk * 16;        // bytes

    float acc[4][4][4];
#pragma unroll
    for (int i = 0; i < 4; ++i)
#pragma unroll
        for (int j = 0; j < 4; ++j)
#pragma unroll
            for (int c = 0; c < 4; ++c) acc[i][j][c] = 0.0f;

    const int T = K / KTILE;

    auto load_tile = [&](int p, int k0) {
        uint32_t dst0 = sbase + (uint32_t)p * STAGE_BYTES;
#pragma unroll
        for (int i = 0; i < 16; ++i) {
            int cid = tid + i * 256;
            int sub = cid >> 10;          // 0:Ahi 1:Alo 2:Bhi 3:Blo
            int idx = cid & 1023;
            int row = idx >> 3;
            int ck = idx & 7;
            int ld_ = (sub < 2) ? lda : ldb;
            const __nv_bfloat16* src = srcs[sub] + (long)row * ld_ + k0 + ck * 8;
            uint32_t off = (uint32_t)(row * 128 + ck * 16);
            cp_async16(dst0 + (uint32_t)sub * TILE_BYTES + SWZ128(off), src);
        }
        asm volatile("cp.async.commit_group;");
    };

    // prologue: stages 0,1
    load_tile(0, 0);
    load_tile(1, KTILE);

    for (int t = 0; t < T; ++t) {
        if (t + 1 < T) asm volatile("cp.async.wait_group 1;");
        else           asm volatile("cp.async.wait_group 0;");
        __syncthreads();
        if (t + 2 < T) load_tile((t + 2) % NSTAGE, (t + 2) * KTILE);

        const uint32_t st = sbase + (uint32_t)(t % NSTAGE) * STAGE_BYTES;
        const uint32_t sa_hi = st;
        const uint32_t sa_lo = st + TILE_BYTES;
        const uint32_t sb_hi = st + 2 * TILE_BYTES;
        const uint32_t sb_lo = st + 3 * TILE_BYTES;

#pragma unroll
        for (int kk = 0; kk < KTILE; kk += 16) {
            const int colb = colb0 + kk * 2;
            uint32_t bh[2][4], bl[2][4], a[4][4];
#pragma unroll
            for (int j = 0; j < 2; ++j) {
                uint32_t off = (uint32_t)((brow + j * 16) * 128 + colb);
                ldsm4(bh[j], sb_hi + SWZ128(off));
                ldsm4(bl[j], sb_lo + SWZ128(off));
            }
#pragma unroll
            for (int mi = 0; mi < 4; ++mi) {
                uint32_t off = (uint32_t)((arow + mi * 16) * 128 + colb);
                ldsm4(a[mi], sa_hi + SWZ128(off));
            }
            // hi*hi and hi*lo
#pragma unroll
            for (int mi = 0; mi < 4; ++mi)
#pragma unroll
                for (int nj = 0; nj < 4; ++nj) {
                    mma_bf16(acc[mi][nj], a[mi], bh[nj >> 1][nj & 1], bh[nj >> 1][2 + (nj & 1)]);
                    mma_bf16(acc[mi][nj], a[mi], bl[nj >> 1][nj & 1], bl[nj >> 1][2 + (nj & 1)]);
                }
            // lo*hi
#pragma unroll
            for (int mi = 0; mi < 4; ++mi) {
                uint32_t off = (uint32_t)((arow + mi * 16) * 128 + colb);
                ldsm4(a[mi], sa_lo + SWZ128(off));
            }
#pragma unroll
            for (int mi = 0; mi < 4; ++mi)
#pragma unroll
                for (int nj = 0; nj < 4; ++nj)
                    mma_bf16(acc[mi][nj], a[mi], bh[nj >> 1][nj & 1], bh[nj >> 1][2 + (nj & 1)]);
        }
    }

    // ---------------- epilogue ----------------
    const int r = lane >> 2;
    const int c = (lane & 3) * 2;
    const int mb = m0 + warp_m * 64;
    const int nb = n0 + warp_n * 32;

#pragma unroll
    for (int mi = 0; mi < 4; ++mi)
#pragma unroll
        for (int nj = 0; nj < 4; ++nj) {
            int row = mb + mi * 16 + r;
            int col = nb + nj * 8 + c;
            float d0 = acc[mi][nj][0], d1 = acc[mi][nj][1];
            float d2 = acc[mi][nj][2], d3 = acc[mi][nj][3];
            if (MODE == 0) {
                float* cp = C + bz * sC + (long)row * ldc + col;
                *reinterpret_cast<float2*>(cp) = make_float2(d0, d1);
                float* cp2 = C + bz * sC + (long)(row + 8) * ldc + col;
                *reinterpret_cast<float2*>(cp2) = make_float2(d2, d3);
            } else {
                long o0 = bz * sC + (long)row * ldc + col;
                long o1 = bz * sC + (long)(row + 8) * ldc + col;
                __nv_bfloat16 h0 = __float2bfloat16(d0), h1 = __float2bfloat16(d1);
                __nv_bfloat16 l0 = __float2bfloat16(d0 - __bfloat162float(h0));
                __nv_bfloat16 l1 = __float2bfloat16(d1 - __bfloat162float(h1));
                *reinterpret_cast<__nv_bfloat162*>(Chi + o0) = __nv_bfloat162(h0, h1);
                *reinterpret_cast<__nv_bfloat162*>(Clo + o0) = __nv_bfloat162(l0, l1);
                __nv_bfloat16 h2 = __float2bfloat16(d2), h3 = __float2bfloat16(d3);
                __nv_bfloat16 l2 = __float2bfloat16(d2 - __bfloat162float(h2));
                __nv_bfloat16 l3 = __float2bfloat16(d3 - __bfloat162float(h3));
                *reinterpret_cast<__nv_bfloat162*>(Chi + o1) = __nv_bfloat162(h2, h3);
                *reinterpret_cast<__nv_bfloat162*>(Clo + o1) = __nv_bfloat162(l2, l3);
            }
        }
}

// ---------------- launch -----------------------------------------------------
extern "C" void kernel_launch(void* const* d_in, const int* in_sizes, int n_in,
                              void* d_out, int out_size) {
    const float* x = (const float*)d_in[0];
    const float* W = (const float*)d_in[1];
    float* out = (float*)d_out;

    const int S = S_DIM, H = H_DIM, B = B_DIM;

    __nv_bfloat16 *xhi, *xlo, *xThi, *xTlo, *WThi, *WTlo, *Ghi, *Glo, *MThi, *MTlo;
    cudaGetSymbolAddress((void**)&xhi, g_xhi);
    cudaGetSymbolAddress((void**)&xlo, g_xlo);
    cudaGetSymbolAddress((void**)&xThi, g_xThi);
    cudaGetSymbolAddress((void**)&xTlo, g_xTlo);
    cudaGetSymbolAddress((void**)&WThi, g_WThi);
    cudaGetSymbolAddress((void**)&WTlo, g_WTlo);
    cudaGetSymbolAddress((void**)&Ghi, g_Ghi);
    cudaGetSymbolAddress((void**)&Glo, g_Glo);
    cudaGetSymbolAddress((void**)&MThi, g_MThi);
    cudaGetSymbolAddress((void**)&MTlo, g_MTlo);

    cudaFuncSetAttribute(gemm_hmma3<0>, cudaFuncAttributeMaxDynamicSharedMemorySize, SMEM_TOT);
    cudaFuncSetAttribute(gemm_hmma3<1>, cudaFuncAttributeMaxDynamicSharedMemorySize, SMEM_TOT);

    // conversions
    {
        int n4 = B * S * H / 4;
        split_kernel<<<(n4 + 255) / 256, 256>>>(x, xhi, xlo, n4);
    }
    transpose_split_kernel<<<dim3(H / 32, S / 32, B), dim3(32, 8)>>>(x, xThi, xTlo, S, H);
    transpose_split_kernel<<<dim3(H / 32, H / 32, 1), dim3(32, 8)>>>(W, WThi, WTlo, H, H);

    // GEMM1: G[o][h] = sum_t xT[o][t] * xT[h][t]   (K = S)
    gemm_hmma3<1><<<dim3(8, 8, B), 256, SMEM_TOT>>>(
        xThi, xTlo, xThi, xTlo, nullptr, Ghi, Glo,
        S, S, S, H, (long)H * S, (long)H * S, (long)H * H);

    // GEMM2: MT[h][k] = sum_o G[h][o] * WT[k][o]   (G symmetric; K = H)
    gemm_hmma3<1><<<dim3(8, 8, B), 256, SMEM_TOT>>>(
        Ghi, Glo, WThi, WTlo, nullptr, MThi, MTlo,
        H, H, H, H, (long)H * H, 0L, (long)H * H);

    // GEMM3: out[s][h] = sum_k x[s][k] * MT[h][k]  (K = H)
    gemm_hmma3<0><<<dim3(8, 32, B), 256, SMEM_TOT>>>(
        xhi, xlo, MThi, MTlo, out, nullptr, nullptr,
        H, H, H, H, (long)S * H, (long)H * H, (long)S * H);
}

// round 9
// speedup vs baseline: 3.2411x; 1.2485x over previous
#include <cuda_runtime.h>
#include <cuda_bf16.h>
#include <cstdint>

#define S_DIM 4096
#define H_DIM 1024
#define B_DIM 4

// ---------------- scratch (__device__ globals; no allocs allowed) -----------
__device__ __nv_bfloat16 g_xhi [B_DIM * S_DIM * H_DIM];
__device__ __nv_bfloat16 g_xlo [B_DIM * S_DIM * H_DIM];
__device__ __nv_bfloat16 g_xThi[B_DIM * H_DIM * S_DIM];
__device__ __nv_bfloat16 g_xTlo[B_DIM * H_DIM * S_DIM];
__device__ __nv_bfloat16 g_WThi[H_DIM * H_DIM];
__device__ __nv_bfloat16 g_WTlo[H_DIM * H_DIM];
__device__ __nv_bfloat16 g_Ghi [B_DIM * H_DIM * H_DIM];
__device__ __nv_bfloat16 g_Glo [B_DIM * H_DIM * H_DIM];
__device__ __nv_bfloat16 g_MThi[B_DIM * H_DIM * H_DIM];
__device__ __nv_bfloat16 g_MTlo[B_DIM * H_DIM * H_DIM];

// ---------------- helpers ----------------------------------------------------
__device__ __forceinline__ uint32_t smem_u32(const void* p) {
    uint32_t a;
    asm("{ .reg .u64 t; cvta.to.shared.u64 t, %1; cvt.u32.u64 %0, t; }"
        : "=r"(a) : "l"(p));
    return a;
}

#define SWZ128(off) ((off) ^ (((off) >> 3) & 0x70))

__device__ __forceinline__ void cp_async16(uint32_t dst, const void* src) {
    asm volatile("cp.async.cg.shared.global [%0], [%1], 16;" :: "r"(dst), "l"(src));
}

__device__ __forceinline__ void ldsm4(uint32_t* r, uint32_t addr) {
    asm volatile("ldmatrix.sync.aligned.m8n8.x4.shared.b16 {%0,%1,%2,%3}, [%4];"
                 : "=r"(r[0]), "=r"(r[1]), "=r"(r[2]), "=r"(r[3]) : "r"(addr));
}

__device__ __forceinline__ void mma_bf16(float* d, const uint32_t* a,
                                         uint32_t b0, uint32_t b1) {
    asm volatile(
        "mma.sync.aligned.m16n8k16.row.col.f32.bf16.bf16.f32 "
        "{%0,%1,%2,%3}, {%4,%5,%6,%7}, {%8,%9}, {%0,%1,%2,%3};"
        : "+f"(d[0]), "+f"(d[1]), "+f"(d[2]), "+f"(d[3])
        : "r"(a[0]), "r"(a[1]), "r"(a[2]), "r"(a[3]), "r"(b0), "r"(b1));
}

__device__ __forceinline__ uint32_t pack_hl(float v, __nv_bfloat16& h, __nv_bfloat16& l) {
    h = __float2bfloat16(v);
    l = __float2bfloat16(v - __bfloat162float(h));
    return ((uint32_t)__bfloat16_as_ushort(h) << 16) | (uint32_t)__bfloat16_as_ushort(l);
}

// ---------------- conversion kernels ----------------------------------------
// in [R][C] -> transposed hi/lo [C][R]; optionally also natural hi/lo [R][C].
// blockDim = (32, 8)
template <bool NAT>
__global__ void transpose_split2_kernel(const float* __restrict__ in,
                                        __nv_bfloat16* __restrict__ hiN,
                                        __nv_bfloat16* __restrict__ loN,
                                        __nv_bfloat16* __restrict__ hiT,
                                        __nv_bfloat16* __restrict__ loT,
                                        int R, int C) {
    __shared__ float tile[32][33];
    long boff = (long)blockIdx.z * R * C;
    const float* src = in + boff;
    int bx = blockIdx.x * 32;
    int by = blockIdx.y * 32;
    int tx = threadIdx.x, ty = threadIdx.y;
#pragma unroll
    for (int j = 0; j < 4; ++j) {
        int row = by + ty + j * 8;
        float v = src[(long)row * C + bx + tx];
        tile[ty + j * 8][tx] = v;
        if (NAT) {
            __nv_bfloat16 h = __float2bfloat16(v);
            __nv_bfloat16 l = __float2bfloat16(v - __bfloat162float(h));
            hiN[boff + (long)row * C + bx + tx] = h;
            loN[boff + (long)row * C + bx + tx] = l;
        }
    }
    __syncthreads();
#pragma unroll
    for (int j = 0; j < 4; ++j) {
        int oc = bx + ty + j * 8;
        int orow = by + tx;
        float v = tile[tx][ty + j * 8];
        __nv_bfloat16 h = __float2bfloat16(v);
        __nv_bfloat16 l = __float2bfloat16(v - __bfloat162float(h));
        hiT[boff + (long)oc * R + orow] = h;
        loT[boff + (long)oc * R + orow] = l;
    }
}

// ---------------- HMMA GEMM ---------------------------------------------------
// C[m][n] = sum_k (Ahi+Alo)[m][k]*(Bhi+Blo)[n][k], 3-term split (lo*lo dropped).
// CTA tile 128x128, KTILE=32 (64B rows, swizzled), 3-stage cp.async, 2 CTA/SM.
// 8 warps (2x4), warp tile 64x32, mma.sync m16n8k16.
// MODE 0: fp32 C.  MODE 1: bf16 hi/lo split.
// MODE 2: bf16 hi/lo split, symmetric (A==B): upper-tri grid + mirrored write.

#define KTILE 32
#define TILE_BYTES 8192               // 128 rows * 64 B
#define STAGE_BYTES (4 * TILE_BYTES)  // Ahi, Alo, Bhi, Blo
#define NSTAGE 3
#define SMEM_TOT (NSTAGE * STAGE_BYTES)   // 96 KB (>= 128*129*4 transpose buf)

template <int MODE>
__global__ __launch_bounds__(256, 2) void gemm_hmma3(
    const __nv_bfloat16* __restrict__ Ahi, const __nv_bfloat16* __restrict__ Alo,
    const __nv_bfloat16* __restrict__ Bhi, const __nv_bfloat16* __restrict__ Blo,
    float* __restrict__ C, __nv_bfloat16* __restrict__ Chi, __nv_bfloat16* __restrict__ Clo,
    int K, int lda, int ldb, int ldc, long sA, long sB, long sC)
{
    extern __shared__ __align__(1024) unsigned char smem[];
    const uint32_t sbase = smem_u32(smem);
    const int tid = threadIdx.x;
    const int wid = tid >> 5;
    const int lane = tid & 31;
    const int warp_m = wid >> 2;   // 0..1
    const int warp_n = wid & 3;    // 0..3
    const int bz = blockIdx.z;

    int m0, n0, bi = 0, bj = 0;
    if (MODE == 2) {
        int r = blockIdx.x;
        while (r >= 8 - bi) { r -= 8 - bi; ++bi; }
        bj = bi + r;
        m0 = bi * 128; n0 = bj * 128;
    } else {
        m0 = blockIdx.y * 128; n0 = blockIdx.x * 128;
    }

    const __nv_bfloat16* srcs[4];
    srcs[0] = Ahi + bz * sA + (long)m0 * lda;
    srcs[1] = Alo + bz * sA + (long)m0 * lda;
    srcs[2] = Bhi + bz * sB + (long)n0 * ldb;
    srcs[3] = Blo + bz * sB + (long)n0 * ldb;

    const int lr = lane & 7;
    const int lg = (lane >> 3) & 1;
    const int lk = (lane >> 4) & 1;
    const int arow = warp_m * 64 + lr + lg * 8;
    const int brow = warp_n * 32 + lr + lg * 8;
    const int colb0 = lk * 16;

    float acc[4][4][4];
#pragma unroll
    for (int i = 0; i < 4; ++i)
#pragma unroll
        for (int j = 0; j < 4; ++j)
#pragma unroll
            for (int c = 0; c < 4; ++c) acc[i][j][c] = 0.0f;

    const int T = K / KTILE;

    auto load_tile = [&](int p, int k0) {
        uint32_t dst0 = sbase + (uint32_t)p * STAGE_BYTES;
#pragma unroll
        for (int i = 0; i < 8; ++i) {
            int cid = tid + i * 256;      // 0..2047
            int sub = cid >> 9;           // 0:Ahi 1:Alo 2:Bhi 3:Blo
            int idx = cid & 511;
            int row = idx >> 2;
            int ck = idx & 3;
            int ld_ = (sub < 2) ? lda : ldb;
            const __nv_bfloat16* src = srcs[sub] + (long)row * ld_ + k0 + ck * 8;
            uint32_t off = (uint32_t)(row * 64 + ck * 16);
            cp_async16(dst0 + (uint32_t)sub * TILE_BYTES + SWZ128(off), src);
        }
        asm volatile("cp.async.commit_group;");
    };

    load_tile(0, 0);
    load_tile(1, KTILE);

    for (int t = 0; t < T; ++t) {
        if (t + 1 < T) asm volatile("cp.async.wait_group 1;");
        else           asm volatile("cp.async.wait_group 0;");
        __syncthreads();
        if (t + 2 < T) load_tile((t + 2) % NSTAGE, (t + 2) * KTILE);

        const uint32_t st = sbase + (uint32_t)(t % NSTAGE) * STAGE_BYTES;
        const uint32_t sa_hi = st;
        const uint32_t sa_lo = st + TILE_BYTES;
        const uint32_t sb_hi = st + 2 * TILE_BYTES;
        const uint32_t sb_lo = st + 3 * TILE_BYTES;

#pragma unroll
        for (int kk = 0; kk < KTILE; kk += 16) {
            const int colb = colb0 + kk * 2;
            uint32_t bh[2][4], bl[2][4], a[4][4];
#pragma unroll
            for (int j = 0; j < 2; ++j) {
                uint32_t off = (uint32_t)((brow + j * 16) * 64 + colb);
                ldsm4(bh[j], sb_hi + SWZ128(off));
                ldsm4(bl[j], sb_lo + SWZ128(off));
            }
#pragma unroll
            for (int mi = 0; mi < 4; ++mi) {
                uint32_t off = (uint32_t)((arow + mi * 16) * 64 + colb);
                ldsm4(a[mi], sa_hi + SWZ128(off));
            }
#pragma unroll
            for (int mi = 0; mi < 4; ++mi)
#pragma unroll
                for (int nj = 0; nj < 4; ++nj) {
                    mma_bf16(acc[mi][nj], a[mi], bh[nj >> 1][nj & 1], bh[nj >> 1][2 + (nj & 1)]);
                    mma_bf16(acc[mi][nj], a[mi], bl[nj >> 1][nj & 1], bl[nj >> 1][2 + (nj & 1)]);
                }
#pragma unroll
            for (int mi = 0; mi < 4; ++mi) {
                uint32_t off = (uint32_t)((arow + mi * 16) * 64 + colb);
                ldsm4(a[mi], sa_lo + SWZ128(off));
            }
#pragma unroll
            for (int mi = 0; mi < 4; ++mi)
#pragma unroll
                for (int nj = 0; nj < 4; ++nj)
                    mma_bf16(acc[mi][nj], a[mi], bh[nj >> 1][nj & 1], bh[nj >> 1][2 + (nj & 1)]);
        }
    }

    // ---------------- epilogue ----------------
    const int r = lane >> 2;
    const int c = (lane & 3) * 2;
    const int mb = m0 + warp_m * 64;
    const int nb = n0 + warp_n * 32;

    if (MODE == 2) __syncthreads();   // pipeline smem dead; tb reuse below
    uint32_t* tb = reinterpret_cast<uint32_t*>(smem);

#pragma unroll
    for (int mi = 0; mi < 4; ++mi)
#pragma unroll
        for (int nj = 0; nj < 4; ++nj) {
            int row = mb + mi * 16 + r;
            int col = nb + nj * 8 + c;
            float d0 = acc[mi][nj][0], d1 = acc[mi][nj][1];
            float d2 = acc[mi][nj][2], d3 = acc[mi][nj][3];
            if (MODE == 0) {
                float* cp = C + bz * sC + (long)row * ldc + col;
                *reinterpret_cast<float2*>(cp) = make_float2(d0, d1);
                float* cp2 = C + bz * sC + (long)(row + 8) * ldc + col;
                *reinterpret_cast<float2*>(cp2) = make_float2(d2, d3);
            } else {
                long o0 = bz * sC + (long)row * ldc + col;
                long o1 = bz * sC + (long)(row + 8) * ldc + col;
                __nv_bfloat16 h0, h1, h2, h3, l0, l1, l2, l3;
                uint32_t p0 = pack_hl(d0, h0, l0);
                uint32_t p1 = pack_hl(d1, h1, l1);
                uint32_t p2 = pack_hl(d2, h2, l2);
                uint32_t p3 = pack_hl(d3, h3, l3);
                *reinterpret_cast<__nv_bfloat162*>(Chi + o0) = __nv_bfloat162(h0, h1);
                *reinterpret_cast<__nv_bfloat162*>(Clo + o0) = __nv_bfloat162(l0, l1);
                *reinterpret_cast<__nv_bfloat162*>(Chi + o1) = __nv_bfloat162(h2, h3);
                *reinterpret_cast<__nv_bfloat162*>(Clo + o1) = __nv_bfloat162(l2, l3);
                if (MODE == 2) {
                    int rl = row - m0, cl = col - n0;
                    tb[rl * 129 + cl] = p0;
                    tb[rl * 129 + cl + 1] = p1;
                    tb[(rl + 8) * 129 + cl] = p2;
                    tb[(rl + 8) * 129 + cl + 1] = p3;
                }
            }
        }

    if (MODE == 2 && bi < bj) {
        __syncthreads();
        // mirrored block at rows [n0, n0+128), cols [m0, m0+128)
        for (int j = tid; j < 8192; j += 256) {
            int rp = j >> 6;
            int cp2 = (j & 63) << 1;
            uint32_t p0 = tb[cp2 * 129 + rp];
            uint32_t p1 = tb[(cp2 + 1) * 129 + rp];
            long o = bz * sC + (long)(n0 + rp) * ldc + (m0 + cp2);
            __nv_bfloat162 hv(__ushort_as_bfloat16((unsigned short)(p0 >> 16)),
                              __ushort_as_bfloat16((unsigned short)(p1 >> 16)));
            __nv_bfloat162 lv(__ushort_as_bfloat16((unsigned short)(p0 & 0xFFFF)),
                              __ushort_as_bfloat16((unsigned short)(p1 & 0xFFFF)));
            *reinterpret_cast<__nv_bfloat162*>(Chi + o) = hv;
            *reinterpret_cast<__nv_bfloat162*>(Clo + o) = lv;
        }
    }
}

// ---------------- launch -----------------------------------------------------
extern "C" void kernel_launch(void* const* d_in, const int* in_sizes, int n_in,
                              void* d_out, int out_size) {
    const float* x = (const float*)d_in[0];
    const float* W = (const float*)d_in[1];
    float* out = (float*)d_out;

    const int S = S_DIM, H = H_DIM, B = B_DIM;

    __nv_bfloat16 *xhi, *xlo, *xThi, *xTlo, *WThi, *WTlo, *Ghi, *Glo, *MThi, *MTlo;
    cudaGetSymbolAddress((void**)&xhi, g_xhi);
    cudaGetSymbolAddress((void**)&xlo, g_xlo);
    cudaGetSymbolAddress((void**)&xThi, g_xThi);
    cudaGetSymbolAddress((void**)&xTlo, g_xTlo);
    cudaGetSymbolAddress((void**)&WThi, g_WThi);
    cudaGetSymbolAddress((void**)&WTlo, g_WTlo);
    cudaGetSymbolAddress((void**)&Ghi, g_Ghi);
    cudaGetSymbolAddress((void**)&Glo, g_Glo);
    cudaGetSymbolAddress((void**)&MThi, g_MThi);
    cudaGetSymbolAddress((void**)&MTlo, g_MTlo);

    cudaFuncSetAttribute(gemm_hmma3<0>, cudaFuncAttributeMaxDynamicSharedMemorySize, SMEM_TOT);
    cudaFuncSetAttribute(gemm_hmma3<1>, cudaFuncAttributeMaxDynamicSharedMemorySize, SMEM_TOT);
    cudaFuncSetAttribute(gemm_hmma3<2>, cudaFuncAttributeMaxDynamicSharedMemorySize, SMEM_TOT);

    // conversions: x -> natural + transposed hi/lo (single pass); W -> transposed
    transpose_split2_kernel<true><<<dim3(H / 32, S / 32, B), dim3(32, 8)>>>(
        x, xhi, xlo, xThi, xTlo, S, H);
    transpose_split2_kernel<false><<<dim3(H / 32, H / 32, 1), dim3(32, 8)>>>(
        W, nullptr, nullptr, WThi, WTlo, H, H);

    // GEMM1 (symmetric): G[o][h] = sum_t xT[o][t]*xT[h][t], upper-tri blocks only
    gemm_hmma3<2><<<dim3(36, 1, B), 256, SMEM_TOT>>>(
        xThi, xTlo, xThi, xTlo, nullptr, Ghi, Glo,
        S, S, S, H, (long)H * S, (long)H * S, (long)H * H);

    // GEMM2: MT[h][k] = sum_o G[h][o] * WT[k][o]   (G symmetric; K = H)
    gemm_hmma3<1><<<dim3(8, 8, B), 256, SMEM_TOT>>>(
        Ghi, Glo, WThi, WTlo, nullptr, MThi, MTlo,
        H, H, H, H, (long)H * H, 0L, (long)H * H);

    // GEMM3: out[s][h] = sum_k x[s][k] * MT[h][k]  (K = H)
    gemm_hmma3<0><<<dim3(8, 32, B), 256, SMEM_TOT>>>(
        xhi, xlo, MThi, MTlo, out, nullptr, nullptr,
        H, H, H, H, (long)S * H, (long)H * H, (long)S * H);
}

// round 10
// speedup vs baseline: 4.8715x; 1.5031x over previous
#include <cuda_runtime.h>
#include <cuda_fp16.h>
#include <cstdint>

#define S_DIM 4096
#define H_DIM 1024
#define B_DIM 4

// ---------------- scratch (__device__ globals; no allocs allowed) -----------
__device__ __half g_xhi [B_DIM * S_DIM * H_DIM];
__device__ __half g_xThi[B_DIM * H_DIM * S_DIM];
__device__ __half g_xTlo[B_DIM * H_DIM * S_DIM];
__device__ __half g_WThi[H_DIM * H_DIM];
__device__ __half g_Ghi [B_DIM * H_DIM * H_DIM];
__device__ __half g_Glo [B_DIM * H_DIM * H_DIM];
__device__ __half g_MThi[B_DIM * H_DIM * H_DIM];
__device__ __half g_MTlo[B_DIM * H_DIM * H_DIM];

// ---------------- helpers ----------------------------------------------------
__device__ __forceinline__ uint32_t smem_u32(const void* p) {
    uint32_t a;
    asm("{ .reg .u64 t; cvta.to.shared.u64 t, %1; cvt.u32.u64 %0, t; }"
        : "=r"(a) : "l"(p));
    return a;
}

#define SWZ128(off) ((off) ^ (((off) >> 3) & 0x70))

__device__ __forceinline__ void cp_async16(uint32_t dst, const void* src) {
    asm volatile("cp.async.cg.shared.global [%0], [%1], 16;" :: "r"(dst), "l"(src));
}

__device__ __forceinline__ void ldsm4(uint32_t* r, uint32_t addr) {
    asm volatile("ldmatrix.sync.aligned.m8n8.x4.shared.b16 {%0,%1,%2,%3}, [%4];"
                 : "=r"(r[0]), "=r"(r[1]), "=r"(r[2]), "=r"(r[3]) : "r"(addr));
}

__device__ __forceinline__ void mma_f16(float* d, const uint32_t* a,
                                        uint32_t b0, uint32_t b1) {
    asm volatile(
        "mma.sync.aligned.m16n8k16.row.col.f32.f16.f16.f32 "
        "{%0,%1,%2,%3}, {%4,%5,%6,%7}, {%8,%9}, {%0,%1,%2,%3};"
        : "+f"(d[0]), "+f"(d[1]), "+f"(d[2]), "+f"(d[3])
        : "r"(a[0]), "r"(a[1]), "r"(a[2]), "r"(a[3]), "r"(b0), "r"(b1));
}

__device__ __forceinline__ uint32_t pack_hl(float v, __half& h, __half& l) {
    h = __float2half_rn(v);
    l = __float2half_rn(v - __half2float(h));
    return ((uint32_t)__half_as_ushort(h) << 16) | (uint32_t)__half_as_ushort(l);
}

// ---------------- conversion kernels ----------------------------------------
// x: natural hi [R][C] + transposed hi/lo [C][R].  blockDim = (32, 8)
__global__ void x_conv_kernel(const float* __restrict__ in,
                              __half* __restrict__ hiN,
                              __half* __restrict__ hiT,
                              __half* __restrict__ loT,
                              int R, int C) {
    __shared__ float tile[32][33];
    long boff = (long)blockIdx.z * R * C;
    const float* src = in + boff;
    int bx = blockIdx.x * 32;
    int by = blockIdx.y * 32;
    int tx = threadIdx.x, ty = threadIdx.y;
#pragma unroll
    for (int j = 0; j < 4; ++j) {
        int row = by + ty + j * 8;
        float v = src[(long)row * C + bx + tx];
        tile[ty + j * 8][tx] = v;
        hiN[boff + (long)row * C + bx + tx] = __float2half_rn(v);
    }
    __syncthreads();
#pragma unroll
    for (int j = 0; j < 4; ++j) {
        int oc = bx + ty + j * 8;
        int orow = by + tx;
        float v = tile[tx][ty + j * 8];
        __half h = __float2half_rn(v);
        __half l = __float2half_rn(v - __half2float(h));
        hiT[boff + (long)oc * R + orow] = h;
        loT[boff + (long)oc * R + orow] = l;
    }
}

// W: transposed hi only, pre-scaled (x4096 to keep fp16 normal).
__global__ void w_conv_kernel(const float* __restrict__ in,
                              __half* __restrict__ hiT, int R, int C, float sc) {
    __shared__ float tile[32][33];
    int bx = blockIdx.x * 32;
    int by = blockIdx.y * 32;
    int tx = threadIdx.x, ty = threadIdx.y;
#pragma unroll
    for (int j = 0; j < 4; ++j)
        tile[ty + j * 8][tx] = in[(long)(by + ty + j * 8) * C + bx + tx];
    __syncthreads();
#pragma unroll
    for (int j = 0; j < 4; ++j) {
        int oc = bx + ty + j * 8;
        int orow = by + tx;
        hiT[(long)oc * R + orow] = __float2half_rn(tile[tx][ty + j * 8] * sc);
    }
}

// ---------------- HMMA 2-term GEMM -------------------------------------------
// SPLITB=false: C = (P0 + P1) * P2^T   (A split, B single)
// SPLITB=true : C = P0 * (P1 + P2)^T   (A single, B split)
// CTA tile 128x128, KTILE=64 fp16 (128B rows, SW128), 2-stage cp.async, 2 CTA/SM.
// MODE 0: fp32 C.  MODE 1: half hi/lo split out.  MODE 2: split out, symmetric.

#define KTILE 64
#define TILE_B 16384                 // 128 rows * 128 B
#define STAGE_B (3 * TILE_B)         // 48 KB
#define NSTAGE 2
#define SMEM_TOT (NSTAGE * STAGE_B)  // 96 KB

template <int MODE, bool SPLITB>
__global__ __launch_bounds__(256, 2) void gemm2t(
    const __half* __restrict__ P0, const __half* __restrict__ P1,
    const __half* __restrict__ P2,
    float* __restrict__ C, __half* __restrict__ Chi, __half* __restrict__ Clo,
    int K, int lda, int ldb, int ldc,
    long s0, long s1, long s2, long sC, float cscale)
{
    extern __shared__ __align__(1024) unsigned char smem[];
    const uint32_t sbase = smem_u32(smem);
    const int tid = threadIdx.x;
    const int wid = tid >> 5;
    const int lane = tid & 31;
    const int warp_m = wid >> 2;
    const int warp_n = wid & 3;
    const int bz = blockIdx.z;

    int m0, n0, bi = 0, bj = 0;
    if (MODE == 2) {
        int r = blockIdx.x;
        while (r >= 8 - bi) { r -= 8 - bi; ++bi; }
        bj = bi + r;
        m0 = bi * 128; n0 = bj * 128;
    } else {
        m0 = blockIdx.y * 128; n0 = blockIdx.x * 128;
    }

    const __half* srcs[3];
    int lds[3];
    srcs[0] = P0 + bz * s0 + (long)m0 * lda;                 lds[0] = lda;
    srcs[1] = P1 + bz * s1 + (SPLITB ? (long)n0 * ldb : (long)m0 * lda);
    lds[1] = SPLITB ? ldb : lda;
    srcs[2] = P2 + bz * s2 + (long)n0 * ldb;                 lds[2] = ldb;

    const int lr = lane & 7;
    const int lg = (lane >> 3) & 1;
    const int lk = (lane >> 4) & 1;
    const int arow = warp_m * 64 + lr + lg * 8;
    const int brow = warp_n * 32 + lr + lg * 8;
    const int colb0 = lk * 16;

    float acc[4][4][4];
#pragma unroll
    for (int i = 0; i < 4; ++i)
#pragma unroll
        for (int j = 0; j < 4; ++j)
#pragma unroll
            for (int c = 0; c < 4; ++c) acc[i][j][c] = 0.0f;

    const int T = K / KTILE;

    auto load_tile = [&](int p, int k0) {
        uint32_t dst0 = sbase + (uint32_t)p * STAGE_B;
#pragma unroll
        for (int i = 0; i < 12; ++i) {
            int cid = tid + i * 256;      // 0..3071
            int sub = cid >> 10;          // 0..2
            int idx = cid & 1023;
            int row = idx >> 3;
            int ck = idx & 7;
            const __half* src = srcs[sub] + (long)row * lds[sub] + k0 + ck * 8;
            uint32_t off = (uint32_t)(row * 128 + ck * 16);
            cp_async16(dst0 + (uint32_t)sub * TILE_B + SWZ128(off), src);
        }
        asm volatile("cp.async.commit_group;");
    };

    load_tile(0, 0);

    for (int t = 0; t < T; ++t) {
        asm volatile("cp.async.wait_group 0;");
        __syncthreads();
        if (t + 1 < T) load_tile((t + 1) & 1, (t + 1) * KTILE);

        const uint32_t st = sbase + (uint32_t)(t & 1) * STAGE_B;
        const uint32_t t0 = st;
        const uint32_t t1 = st + TILE_B;
        const uint32_t t2 = st + 2 * TILE_B;

#pragma unroll
        for (int kk = 0; kk < KTILE; kk += 16) {
            const int colb = colb0 + kk * 2;
            uint32_t a[4][4], b0f[2][4], b1f[2][4];
            if (SPLITB) {
                // A single (t0); B split (t1 hi, t2 lo)
#pragma unroll
                for (int mi = 0; mi < 4; ++mi) {
                    uint32_t off = (uint32_t)((arow + mi * 16) * 128 + colb);
                    ldsm4(a[mi], t0 + SWZ128(off));
                }
#pragma unroll
                for (int j = 0; j < 2; ++j) {
                    uint32_t off = (uint32_t)((brow + j * 16) * 128 + colb);
                    ldsm4(b0f[j], t1 + SWZ128(off));
                    ldsm4(b1f[j], t2 + SWZ128(off));
                }
#pragma unroll
                for (int mi = 0; mi < 4; ++mi)
#pragma unroll
                    for (int nj = 0; nj < 4; ++nj) {
                        mma_f16(acc[mi][nj], a[mi], b0f[nj >> 1][nj & 1], b0f[nj >> 1][2 + (nj & 1)]);
                        mma_f16(acc[mi][nj], a[mi], b1f[nj >> 1][nj & 1], b1f[nj >> 1][2 + (nj & 1)]);
                    }
            } else {
                // A split (t0 hi, t1 lo); B single (t2)
#pragma unroll
                for (int j = 0; j < 2; ++j) {
                    uint32_t off = (uint32_t)((brow + j * 16) * 128 + colb);
                    ldsm4(b0f[j], t2 + SWZ128(off));
                }
#pragma unroll
                for (int mi = 0; mi < 4; ++mi) {
                    uint32_t off = (uint32_t)((arow + mi * 16) * 128 + colb);
                    ldsm4(a[mi], t0 + SWZ128(off));
                }
#pragma unroll
                for (int mi = 0; mi < 4; ++mi)
#pragma unroll
                    for (int nj = 0; nj < 4; ++nj)
                        mma_f16(acc[mi][nj], a[mi], b0f[nj >> 1][nj & 1], b0f[nj >> 1][2 + (nj & 1)]);
#pragma unroll
                for (int mi = 0; mi < 4; ++mi) {
                    uint32_t off = (uint32_t)((arow + mi * 16) * 128 + colb);
                    ldsm4(a[mi], t1 + SWZ128(off));
                }
#pragma unroll
                for (int mi = 0; mi < 4; ++mi)
#pragma unroll
                    for (int nj = 0; nj < 4; ++nj)
                        mma_f16(acc[mi][nj], a[mi], b0f[nj >> 1][nj & 1], b0f[nj >> 1][2 + (nj & 1)]);
            }
        }
    }

    // ---------------- epilogue ----------------
    const int r = lane >> 2;
    const int c = (lane & 3) * 2;
    const int mb = m0 + warp_m * 64;
    const int nb = n0 + warp_n * 32;

    if (MODE == 2) __syncthreads();   // pipeline smem dead; tb reuse below
    uint32_t* tb = reinterpret_cast<uint32_t*>(smem);

#pragma unroll
    for (int mi = 0; mi < 4; ++mi)
#pragma unroll
        for (int nj = 0; nj < 4; ++nj) {
            int row = mb + mi * 16 + r;
            int col = nb + nj * 8 + c;
            float d0 = acc[mi][nj][0] * cscale, d1 = acc[mi][nj][1] * cscale;
            float d2 = acc[mi][nj][2] * cscale, d3 = acc[mi][nj][3] * cscale;
            if (MODE == 0) {
                float* cp = C + bz * sC + (long)row * ldc + col;
                *reinterpret_cast<float2*>(cp) = make_float2(d0, d1);
                float* cp2 = C + bz * sC + (long)(row + 8) * ldc + col;
                *reinterpret_cast<float2*>(cp2) = make_float2(d2, d3);
            } else {
                long o0 = bz * sC + (long)row * ldc + col;
                long o1 = bz * sC + (long)(row + 8) * ldc + col;
                __half h0, h1, h2, h3, l0, l1, l2, l3;
                uint32_t p0 = pack_hl(d0, h0, l0);
                uint32_t p1 = pack_hl(d1, h1, l1);
                uint32_t p2 = pack_hl(d2, h2, l2);
                uint32_t p3 = pack_hl(d3, h3, l3);
                *reinterpret_cast<__half2*>(Chi + o0) = __half2(h0, h1);
                *reinterpret_cast<__half2*>(Clo + o0) = __half2(l0, l1);
                *reinterpret_cast<__half2*>(Chi + o1) = __half2(h2, h3);
                *reinterpret_cast<__half2*>(Clo + o1) = __half2(l2, l3);
                if (MODE == 2) {
                    int rl = row - m0, cl = col - n0;
                    tb[rl * 129 + cl] = p0;
                    tb[rl * 129 + cl + 1] = p1;
                    tb[(rl + 8) * 129 + cl] = p2;
                    tb[(rl + 8) * 129 + cl + 1] = p3;
                }
            }
        }

    if (MODE == 2 && bi < bj) {
        __syncthreads();
        for (int j = tid; j < 8192; j += 256) {
            int rp = j >> 6;
            int cp2 = (j & 63) << 1;
            uint32_t p0 = tb[cp2 * 129 + rp];
            uint32_t p1 = tb[(cp2 + 1) * 129 + rp];
            long o = bz * sC + (long)(n0 + rp) * ldc + (m0 + cp2);
            __half2 hv(__ushort_as_half((unsigned short)(p0 >> 16)),
                       __ushort_as_half((unsigned short)(p1 >> 16)));
            __half2 lv(__ushort_as_half((unsigned short)(p0 & 0xFFFF)),
                       __ushort_as_half((unsigned short)(p1 & 0xFFFF)));
            *reinterpret_cast<__half2*>(Chi + o) = hv;
            *reinterpret_cast<__half2*>(Clo + o) = lv;
        }
    }
}

// ---------------- launch -----------------------------------------------------
extern "C" void kernel_launch(void* const* d_in, const int* in_sizes, int n_in,
                              void* d_out, int out_size) {
    const float* x = (const float*)d_in[0];
    const float* W = (const float*)d_in[1];
    float* out = (float*)d_out;

    const int S = S_DIM, H = H_DIM, B = B_DIM;
    const long HS = (long)H * S, HH = (long)H * H, SH = (long)S * H;

    __half *xhi, *xThi, *xTlo, *WThi, *Ghi, *Glo, *MThi, *MTlo;
    cudaGetSymbolAddress((void**)&xhi, g_xhi);
    cudaGetSymbolAddress((void**)&xThi, g_xThi);
    cudaGetSymbolAddress((void**)&xTlo, g_xTlo);
    cudaGetSymbolAddress((void**)&WThi, g_WThi);
    cudaGetSymbolAddress((void**)&Ghi, g_Ghi);
    cudaGetSymbolAddress((void**)&Glo, g_Glo);
    cudaGetSymbolAddress((void**)&MThi, g_MThi);
    cudaGetSymbolAddress((void**)&MTlo, g_MTlo);

    cudaFuncSetAttribute(gemm2t<0, true>,  cudaFuncAttributeMaxDynamicSharedMemorySize, SMEM_TOT);
    cudaFuncSetAttribute(gemm2t<1, false>, cudaFuncAttributeMaxDynamicSharedMemorySize, SMEM_TOT);
    cudaFuncSetAttribute(gemm2t<2, false>, cudaFuncAttributeMaxDynamicSharedMemorySize, SMEM_TOT);

    // conversions
    x_conv_kernel<<<dim3(H / 32, S / 32, B), dim3(32, 8)>>>(x, xhi, xThi, xTlo, S, H);
    w_conv_kernel<<<dim3(H / 32, H / 32, 1), dim3(32, 8)>>>(W, WThi, H, H, 4096.0f);

    // GEMM1 (symmetric): G = (xThi+xTlo) . xThi^T   K=S, upper-tri blocks
    gemm2t<2, false><<<dim3(36, 1, B), 256, SMEM_TOT>>>(
        xThi, xTlo, xThi, nullptr, Ghi, Glo,
        S, S, S, H, HS, HS, HS, HH, 1.0f);

    // GEMM2: MT' = (Ghi+Glo) . WThi^T ; W scaled 2^12, store MT*16 => cscale 2^-8
    gemm2t<1, false><<<dim3(8, 8, B), 256, SMEM_TOT>>>(
        Ghi, Glo, WThi, nullptr, MThi, MTlo,
        H, H, H, H, HH, HH, 0L, HH, 1.0f / 256.0f);

    // GEMM3: out = xhi . (MThi+MTlo)^T ; MT carries *16 => cscale 2^-4
    gemm2t<0, true><<<dim3(8, 32, B), 256, SMEM_TOT>>>(
        xhi, MThi, MTlo, out, nullptr, nullptr,
        H, H, H, H, SH, HH, HH, SH, 1.0f / 16.0f);
}

// round 11
// speedup vs baseline: 6.9029x; 1.4170x over previous
#include <cuda_runtime.h>
#include <cuda_fp16.h>
#include <cstdint>

#define S_DIM 4096
#define H_DIM 1024
#define B_DIM 4

// ---------------- scratch (__device__ globals; no allocs allowed) -----------
__device__ __half g_xhi [B_DIM * S_DIM * H_DIM];
__device__ __half g_xThi[B_DIM * H_DIM * S_DIM];
__device__ __half g_xTlo[B_DIM * H_DIM * S_DIM];
__device__ __half g_WThi[H_DIM * H_DIM];
__device__ __half g_Ghi [B_DIM * H_DIM * H_DIM];
__device__ __half g_MThi[B_DIM * H_DIM * H_DIM];

// ---------------- helpers ----------------------------------------------------
__device__ __forceinline__ uint32_t smem_u32(const void* p) {
    uint32_t a;
    asm("{ .reg .u64 t; cvta.to.shared.u64 t, %1; cvt.u32.u64 %0, t; }"
        : "=r"(a) : "l"(p));
    return a;
}

#define SWZ128(off) ((off) ^ (((off) >> 3) & 0x70))

__device__ __forceinline__ void cp_async16(uint32_t dst, const void* src) {
    asm volatile("cp.async.cg.shared.global [%0], [%1], 16;" :: "r"(dst), "l"(src));
}

__device__ __forceinline__ void ldsm4(uint32_t* r, uint32_t addr) {
    asm volatile("ldmatrix.sync.aligned.m8n8.x4.shared.b16 {%0,%1,%2,%3}, [%4];"
                 : "=r"(r[0]), "=r"(r[1]), "=r"(r[2]), "=r"(r[3]) : "r"(addr));
}

__device__ __forceinline__ void mma_f16(float* d, const uint32_t* a,
                                        uint32_t b0, uint32_t b1) {
    asm volatile(
        "mma.sync.aligned.m16n8k16.row.col.f32.f16.f16.f32 "
        "{%0,%1,%2,%3}, {%4,%5,%6,%7}, {%8,%9}, {%0,%1,%2,%3};"
        : "+f"(d[0]), "+f"(d[1]), "+f"(d[2]), "+f"(d[3])
        : "r"(a[0]), "r"(a[1]), "r"(a[2]), "r"(a[3]), "r"(b0), "r"(b1));
}

// ---------------- conversion kernels ----------------------------------------
// x: natural hi [R][C] + transposed hi/lo [C][R].  blockDim = (32, 8)
__global__ void x_conv_kernel(const float* __restrict__ in,
                              __half* __restrict__ hiN,
                              __half* __restrict__ hiT,
                              __half* __restrict__ loT,
                              int R, int C) {
    __shared__ float tile[32][33];
    long boff = (long)blockIdx.z * R * C;
    const float* src = in + boff;
    int bx = blockIdx.x * 32;
    int by = blockIdx.y * 32;
    int tx = threadIdx.x, ty = threadIdx.y;
#pragma unroll
    for (int j = 0; j < 4; ++j) {
        int row = by + ty + j * 8;
        float v = src[(long)row * C + bx + tx];
        tile[ty + j * 8][tx] = v;
        hiN[boff + (long)row * C + bx + tx] = __float2half_rn(v);
    }
    __syncthreads();
#pragma unroll
    for (int j = 0; j < 4; ++j) {
        int oc = bx + ty + j * 8;
        int orow = by + tx;
        float v = tile[tx][ty + j * 8];
        __half h = __float2half_rn(v);
        __half l = __float2half_rn(v - __half2float(h));
        hiT[boff + (long)oc * R + orow] = h;
        loT[boff + (long)oc * R + orow] = l;
    }
}

// W: transposed hi only, pre-scaled (x4096 keeps fp16 normal).
__global__ void w_conv_kernel(const float* __restrict__ in,
                              __half* __restrict__ hiT, int R, int C, float sc) {
    __shared__ float tile[32][33];
    int bx = blockIdx.x * 32;
    int by = blockIdx.y * 32;
    int tx = threadIdx.x, ty = threadIdx.y;
#pragma unroll
    for (int j = 0; j < 4; ++j)
        tile[ty + j * 8][tx] = in[(long)(by + ty + j * 8) * C + bx + tx];
    __syncthreads();
#pragma unroll
    for (int j = 0; j < 4; ++j) {
        int oc = bx + ty + j * 8;
        int orow = by + tx;
        hiT[(long)oc * R + orow] = __float2half_rn(tile[tx][ty + j * 8] * sc);
    }
}

// ---------------- HMMA GEMM ---------------------------------------------------
// ASPLIT=true : C = (P0 + P1) * PB^T  (A hi/lo split, 2 terms, 2-stage pipeline)
// ASPLIT=false: C = P0 * PB^T         (single term, 3-stage pipeline)
// CTA tile 128x128, KTILE=64 fp16 (128B rows, SW128), 2 CTA/SM, 8 warps 2x4.
// MODE 0: fp32 C.  MODE 1: fp16 C.  MODE 2: fp16 C, symmetric mirror (A==B).

#define KTILE 64
#define TILE_B 16384                 // 128 rows * 128 B
#define SMEM_TOT 98304               // 96 KB either way

template <int MODE, bool ASPLIT>
__global__ __launch_bounds__(256, 2) void gemm_hmma(
    const __half* __restrict__ P0, const __half* __restrict__ P1,
    const __half* __restrict__ PB,
    float* __restrict__ C, __half* __restrict__ Ch,
    int K, int lda, int ldb, int ldc,
    long s0, long s1, long sB, long sC, float cscale)
{
    constexpr int NT = ASPLIT ? 3 : 2;
    constexpr int NSTAGE = ASPLIT ? 2 : 3;
    constexpr uint32_t STAGE_B = NT * TILE_B;

    extern __shared__ __align__(1024) unsigned char smem[];
    const uint32_t sbase = smem_u32(smem);
    const int tid = threadIdx.x;
    const int wid = tid >> 5;
    const int lane = tid & 31;
    const int warp_m = wid >> 2;
    const int warp_n = wid & 3;
    const int bz = blockIdx.z;

    int m0, n0, bi = 0, bj = 0;
    if (MODE == 2) {
        int r = blockIdx.x;
        while (r >= 8 - bi) { r -= 8 - bi; ++bi; }
        bj = bi + r;
        m0 = bi * 128; n0 = bj * 128;
    } else {
        m0 = blockIdx.y * 128; n0 = blockIdx.x * 128;
    }

    const __half* srcs[NT];
    int lds[NT];
    srcs[0] = P0 + bz * s0 + (long)m0 * lda;  lds[0] = lda;
    if (ASPLIT) { srcs[1] = P1 + bz * s1 + (long)m0 * lda; lds[1] = lda; }
    srcs[NT - 1] = PB + bz * sB + (long)n0 * ldb;  lds[NT - 1] = ldb;

    const int lr = lane & 7;
    const int lg = (lane >> 3) & 1;
    const int lk = (lane >> 4) & 1;
    const int arow = warp_m * 64 + lr + lg * 8;
    const int brow = warp_n * 32 + lr + lg * 8;
    const int colb0 = lk * 16;

    float acc[4][4][4];
#pragma unroll
    for (int i = 0; i < 4; ++i)
#pragma unroll
        for (int j = 0; j < 4; ++j)
#pragma unroll
            for (int c = 0; c < 4; ++c) acc[i][j][c] = 0.0f;

    const int T = K / KTILE;

    auto load_tile = [&](int p, int k0) {
        uint32_t dst0 = sbase + (uint32_t)p * STAGE_B;
#pragma unroll
        for (int i = 0; i < NT * 4; ++i) {
            int cid = tid + i * 256;
            int sub = cid >> 10;
            int idx = cid & 1023;
            int row = idx >> 3;
            int ck = idx & 7;
            const __half* src = srcs[sub] + (long)row * lds[sub] + k0 + ck * 8;
            uint32_t off = (uint32_t)(row * 128 + ck * 16);
            cp_async16(dst0 + (uint32_t)sub * TILE_B + SWZ128(off), src);
        }
        asm volatile("cp.async.commit_group;");
    };

    load_tile(0, 0);
    if (NSTAGE == 3 && T > 1) load_tile(1, KTILE);

    for (int t = 0; t < T; ++t) {
        if (NSTAGE == 3) {
            if (t + 1 < T) asm volatile("cp.async.wait_group 1;");
            else           asm volatile("cp.async.wait_group 0;");
        } else {
            asm volatile("cp.async.wait_group 0;");
        }
        __syncthreads();
        int nxt = t + (NSTAGE == 3 ? 2 : 1);
        if (nxt < T) load_tile(nxt % NSTAGE, nxt * KTILE);

        const uint32_t st = sbase + (uint32_t)(t % NSTAGE) * STAGE_B;
        const uint32_t ta_hi = st;
        const uint32_t ta_lo = st + TILE_B;            // ASPLIT only
        const uint32_t tb_   = st + (NT - 1) * TILE_B;

#pragma unroll
        for (int kk = 0; kk < KTILE; kk += 16) {
            const int colb = colb0 + kk * 2;
            uint32_t a[4][4], bf[2][4];
#pragma unroll
            for (int j = 0; j < 2; ++j) {
                uint32_t off = (uint32_t)((brow + j * 16) * 128 + colb);
                ldsm4(bf[j], tb_ + SWZ128(off));
            }
#pragma unroll
            for (int mi = 0; mi < 4; ++mi) {
                uint32_t off = (uint32_t)((arow + mi * 16) * 128 + colb);
                ldsm4(a[mi], ta_hi + SWZ128(off));
            }
#pragma unroll
            for (int mi = 0; mi < 4; ++mi)
#pragma unroll
                for (int nj = 0; nj < 4; ++nj)
                    mma_f16(acc[mi][nj], a[mi], bf[nj >> 1][nj & 1], bf[nj >> 1][2 + (nj & 1)]);
            if (ASPLIT) {
#pragma unroll
                for (int mi = 0; mi < 4; ++mi) {
                    uint32_t off = (uint32_t)((arow + mi * 16) * 128 + colb);
                    ldsm4(a[mi], ta_lo + SWZ128(off));
                }
#pragma unroll
                for (int mi = 0; mi < 4; ++mi)
#pragma unroll
                    for (int nj = 0; nj < 4; ++nj)
                        mma_f16(acc[mi][nj], a[mi], bf[nj >> 1][nj & 1], bf[nj >> 1][2 + (nj & 1)]);
            }
        }
    }

    // ---------------- epilogue ----------------
    const int r = lane >> 2;
    const int c = (lane & 3) * 2;
    const int mb = m0 + warp_m * 64;
    const int nb = n0 + warp_n * 32;

    if (MODE == 2) __syncthreads();   // pipeline smem dead; tb buffer reuse
    unsigned short* tbuf = reinterpret_cast<unsigned short*>(smem);

#pragma unroll
    for (int mi = 0; mi < 4; ++mi)
#pragma unroll
        for (int nj = 0; nj < 4; ++nj) {
            int row = mb + mi * 16 + r;
            int col = nb + nj * 8 + c;
            float d0 = acc[mi][nj][0] * cscale, d1 = acc[mi][nj][1] * cscale;
            float d2 = acc[mi][nj][2] * cscale, d3 = acc[mi][nj][3] * cscale;
            if (MODE == 0) {
                float* cp = C + bz * sC + (long)row * ldc + col;
                *reinterpret_cast<float2*>(cp) = make_float2(d0, d1);
                float* cp2 = C + bz * sC + (long)(row + 8) * ldc + col;
                *reinterpret_cast<float2*>(cp2) = make_float2(d2, d3);
            } else {
                long o0 = bz * sC + (long)row * ldc + col;
                long o1 = bz * sC + (long)(row + 8) * ldc + col;
                __half h0 = __float2half_rn(d0), h1 = __float2half_rn(d1);
                __half h2 = __float2half_rn(d2), h3 = __float2half_rn(d3);
                *reinterpret_cast<__half2*>(Ch + o0) = __half2(h0, h1);
                *reinterpret_cast<__half2*>(Ch + o1) = __half2(h2, h3);
                if (MODE == 2) {
                    int rl = row - m0, cl = col - n0;
                    tbuf[rl * 130 + cl] = __half_as_ushort(h0);
                    tbuf[rl * 130 + cl + 1] = __half_as_ushort(h1);
                    tbuf[(rl + 8) * 130 + cl] = __half_as_ushort(h2);
                    tbuf[(rl + 8) * 130 + cl + 1] = __half_as_ushort(h3);
                }
            }
        }

    if (MODE == 2 && bi < bj) {
        __syncthreads();
        for (int j = tid; j < 8192; j += 256) {
            int rp = j >> 6;
            int cp2 = (j & 63) << 1;
            __half2 hv(__ushort_as_half(tbuf[cp2 * 130 + rp]),
                       __ushort_as_half(tbuf[(cp2 + 1) * 130 + rp]));
            long o = bz * sC + (long)(n0 + rp) * ldc + (m0 + cp2);
            *reinterpret_cast<__half2*>(Ch + o) = hv;
        }
    }
}

// ---------------- launch -----------------------------------------------------
extern "C" void kernel_launch(void* const* d_in, const int* in_sizes, int n_in,
                              void* d_out, int out_size) {
    const float* x = (const float*)d_in[0];
    const float* W = (const float*)d_in[1];
    float* out = (float*)d_out;

    const int S = S_DIM, H = H_DIM, B = B_DIM;
    const long HS = (long)H * S, HH = (long)H * H, SH = (long)S * H;

    __half *xhi, *xThi, *xTlo, *WThi, *Ghi, *MThi;
    cudaGetSymbolAddress((void**)&xhi, g_xhi);
    cudaGetSymbolAddress((void**)&xThi, g_xThi);
    cudaGetSymbolAddress((void**)&xTlo, g_xTlo);
    cudaGetSymbolAddress((void**)&WThi, g_WThi);
    cudaGetSymbolAddress((void**)&Ghi, g_Ghi);
    cudaGetSymbolAddress((void**)&MThi, g_MThi);

    cudaFuncSetAttribute(gemm_hmma<2, true>,  cudaFuncAttributeMaxDynamicSharedMemorySize, SMEM_TOT);
    cudaFuncSetAttribute(gemm_hmma<1, false>, cudaFuncAttributeMaxDynamicSharedMemorySize, SMEM_TOT);
    cudaFuncSetAttribute(gemm_hmma<0, false>, cudaFuncAttributeMaxDynamicSharedMemorySize, SMEM_TOT);

    // conversions
    x_conv_kernel<<<dim3(H / 32, S / 32, B), dim3(32, 8)>>>(x, xhi, xThi, xTlo, S, H);
    w_conv_kernel<<<dim3(H / 32, H / 32, 1), dim3(32, 8)>>>(W, WThi, H, H, 4096.0f);

    // GEMM1 (symmetric, A split): G = (xThi+xTlo) . xThi^T,  K=S, upper-tri
    gemm_hmma<2, true><<<dim3(36, 1, B), 256, SMEM_TOT>>>(
        xThi, xTlo, xThi, nullptr, Ghi,
        S, S, S, H, HS, HS, HS, HH, 1.0f);

    // GEMM2 (single): MT[h][k] = G[h][.] . WT[k][.]^T ; carries W's x4096 scale
    gemm_hmma<1, false><<<dim3(8, 8, B), 256, SMEM_TOT>>>(
        Ghi, nullptr, WThi, nullptr, MThi,
        H, H, H, H, HH, 0L, 0L, HH, 1.0f);

    // GEMM3 (single): out = xhi . MT^T ; undo x4096
    gemm_hmma<0, false><<<dim3(8, 32, B), 256, SMEM_TOT>>>(
        xhi, nullptr, MThi, out, nullptr,
        H, H, H, H, SH, 0L, HH, SH, 1.0f / 4096.0f);
}